// round 16
// baseline (speedup 1.0000x reference)
#include <cuda_runtime.h>
#include <cuda_fp16.h>
#include <cstdint>

// out[b,k] = sum_ij in1[b,i]*in2[b,j]*cb[k,ij]
// R14 lineage (1 row/thread, fp16 P in shared, constant-port meta, fixed
// 4 nnz/k, overflow list) re-tuned per R15 finding (warp count binds):
//  - TPB 128, CHUNK 8 (k padded to 88): smem 24,960 B -> up to 9 CTAs/SM.
//  - flush: bl=t>>3, kq=t&7, constant deltas, NO wrap predicate; phases 0..9
//    need no k-bound check (ph*8+7 <= 79 < 81); full-CTA path skips g<limit.
//  - O fp32, stride 132: STS consecutive, flush LDS (4kq+bl)%32 injective ->
//    conflict-free both ways; restores rel_err to ~2e-4 (no O quantization).

#define NK     81
#define NIJ    81
#define TPB    128
#define CHUNK  8
#define NPH    11
#define KPAD   (NPH * CHUNK)     // 88
#define OSTR   132               // O stride in floats

#define P_BYTES  (NIJ * TPB * 2)          // 20,736
#define O_BYTES  (CHUNK * OSTR * 4)       // 4,224
#define SMEM_TOT (P_BYTES + O_BYTES)      // 24,960

struct Tbl {
    float4 meta[KPAD][2];   // per k: {P_byteoff0,w0,off1,w1} x2 (off = ij*256)
    int    ovp[NPH + 1];    // overflow rowptr per phase
    int    pad[3];
};

__device__ Tbl    g_stage;
__device__ float4 g_ovf[NK * NIJ];   // {o_byteoff (kl*528), p_byteoff, w, 0}
__constant__ Tbl  c_tbl;

__global__ void prep_kernel(const float* __restrict__ cb) {
    __shared__ int ocnt[NK];
    __shared__ int ooff[NK + 1];
    const int k = threadIdx.x;
    if (k < NK) {
        int c = 0;
        for (int ij = 0; ij < NIJ; ij++)
            if (cb[k * NIJ + ij] != 0.f) c++;
        ocnt[k] = (c > 4) ? (c - 4) : 0;
    }
    __syncthreads();
    if (k == 0) {
        int s = 0;
        for (int q = 0; q < NK; q++) { ooff[q] = s; s += ocnt[q]; }
        ooff[NK] = s;
        for (int p = 0; p <= NPH; p++) {
            int kb = p * CHUNK; if (kb > NK) kb = NK;
            g_stage.ovp[p] = ooff[kb];
        }
    }
    __syncthreads();
    if (k < KPAD) {
        float id[4] = {0.f, 0.f, 0.f, 0.f};
        float w [4] = {0.f, 0.f, 0.f, 0.f};
        if (k < NK) {
            int n = 0;
            int o = ooff[k];
            const int kl = k & (CHUNK - 1);
            for (int ij = 0; ij < NIJ; ij++) {
                float v = cb[k * NIJ + ij];
                if (v != 0.f) {
                    if (n < 4) { id[n] = __int_as_float(ij * TPB * 2); w[n] = v; n++; }
                    else g_ovf[o++] = make_float4(__int_as_float(kl * OSTR * 4),
                                                  __int_as_float(ij * TPB * 2), v, 0.f);
                }
            }
        }
        g_stage.meta[k][0] = make_float4(id[0], w[0], id[1], w[1]);
        g_stage.meta[k][1] = make_float4(id[2], w[2], id[3], w[3]);
    }
}

__global__ void __launch_bounds__(TPB, 9) tp_kernel(
    const float* __restrict__ in1,
    const float* __restrict__ in2,
    float* __restrict__ out,
    int B)
{
    extern __shared__ char smemc[];
    __half* P   = (__half*)smemc;                  // [81][128] halves
    float*  O   = (float*)(smemc + P_BYTES);       // [8][132] floats
    float*  st1 = (float*)smemc;                   // staging (P region)
    float*  st2 = (float*)(smemc + TPB * 9 * 4);   // +4608 B, 16B-aligned

    const int t = threadIdx.x;
    const int base = blockIdx.x * TPB;

    // ---- coalesced input staging into the (not-yet-used) P region ----
    const int avail = B * 9 - base * 9;
    if (avail >= TPB * 9) {
        const float4* v1 = (const float4*)(in1 + base * 9);  // base*36 % 16 == 0
        const float4* v2 = (const float4*)(in2 + base * 9);
        float4* s1 = (float4*)st1;
        float4* s2 = (float4*)st2;
#pragma unroll
        for (int q = t; q < (TPB * 9) / 4; q += TPB) { s1[q] = v1[q]; s2[q] = v2[q]; }
    } else {
        for (int q = t; q < TPB * 9; q += TPB) {
            bool ok = q < avail;
            st1[q] = ok ? in1[base * 9 + q] : 0.f;
            st2[q] = ok ? in2[base * 9 + q] : 0.f;
        }
    }
    __syncthreads();

    float a[9], c9[9];                 // bank 9t+i mod 32, gcd(9,32)=1: clean
#pragma unroll
    for (int i = 0; i < 9; i++) { a[i] = st1[t * 9 + i]; c9[i] = st2[t * 9 + i]; }
    __syncthreads();                   // staging consumed; P region free

    // outer product -> fp16 P, own column (only this thread reads it)
    char* Pb = (char*)P + t * 2;
#pragma unroll
    for (int i = 0; i < 9; i++)
#pragma unroll
        for (int j = 0; j < 9; j++)
            *(__half*)(Pb + (i * 9 + j) * (TPB * 2)) = __float2half_rn(a[i] * c9[j]);

    const int limit  = B * NK;                   // 84,934,656 < 2^31
    const int gbase0 = blockIdx.x * TPB * NK;
    const bool full  = (base + TPB) * NK <= limit;
    char* Ob = (char*)O + t * 4;

    const int bl0 = t >> 3;            // flush: fixed per-thread decomposition
    const int kq0 = t & 7;

#pragma unroll
    for (int ph = 0; ph < NPH; ph++) {
        // ---- contraction: fixed 4 nnz per k, immediate constant addresses ----
#pragma unroll
        for (int kq = 0; kq < CHUNK; kq++) {
            const float4 m0 = c_tbl.meta[ph * CHUNK + kq][0];
            const float4 m1 = c_tbl.meta[ph * CHUNK + kq][1];
            float p0 = __half2float(*(const __half*)(Pb + __float_as_int(m0.x)));
            float p1 = __half2float(*(const __half*)(Pb + __float_as_int(m0.z)));
            float p2 = __half2float(*(const __half*)(Pb + __float_as_int(m1.x)));
            float p3 = __half2float(*(const __half*)(Pb + __float_as_int(m1.z)));
            float s0 = m0.y * p0;
            float s1 = m0.w * p1;
            s0 = fmaf(m1.y, p2, s0);
            s1 = fmaf(m1.w, p3, s1);
            *(float*)(Ob + kq * (OSTR * 4)) = s0 + s1;   // STS consecutive-t
        }
        // ---- rare overflow entries (rows with >4 nnz), own-column += ----
        {
            const int r1 = c_tbl.ovp[ph + 1];
#pragma unroll 1
            for (int r = c_tbl.ovp[ph]; r < r1; r++) {
                const float4 e = g_ovf[r];
                float pv = __half2float(*(const __half*)(Pb + __float_as_int(e.y)));
                float* op = (float*)(Ob + __float_as_int(e.x));
                *op = fmaf(e.z, pv, *op);
            }
        }
        __syncthreads();   // flush reads other threads' O columns

        // ---- flush: conflict-free LDS, constant deltas, coalesced STG ----
        if (ph < 10) {
            int si = kq0 * OSTR + bl0;                 // (4kq+bl)%32 injective
            int g  = gbase0 + bl0 * NK + ph * CHUNK + kq0;
            if (full) {
#pragma unroll
                for (int r = 0; r < TPB / 16; r++) {   // 8 iters: 16 rows/iter
                    out[g] = O[si];
                    g  += 16 * NK;                     // 1296
                    si += 16;
                }
            } else {
#pragma unroll
                for (int r = 0; r < TPB / 16; r++) {
                    if (g < limit) out[g] = O[si];
                    g  += 16 * NK;
                    si += 16;
                }
            }
        } else {            // ph == 10: only k = 80 (kq0 == 0) is real
            if (kq0 == 0) {
                int si = bl0;
                int g  = gbase0 + bl0 * NK + 80;
#pragma unroll
                for (int r = 0; r < TPB / 16; r++) {
                    if (g < limit) out[g] = O[si];
                    g  += 16 * NK;
                    si += 16;
                }
            }
        }
        __syncthreads();   // next phase reuses O
    }
}

extern "C" void kernel_launch(void* const* d_in, const int* in_sizes, int n_in,
                              void* d_out, int out_size) {
    const float* in1 = (const float*)d_in[0];
    const float* in2 = (const float*)d_in[1];
    const float* cb  = (const float*)d_in[2];
    float* out = (float*)d_out;

    const int B = in_sizes[0] / 9;
    const int grid = (B + TPB - 1) / TPB;

    cudaFuncSetAttribute(tp_kernel,
                         cudaFuncAttributeMaxDynamicSharedMemorySize,
                         SMEM_TOT);      // 24,960 B -> 8-9 CTAs/SM

    prep_kernel<<<1, 128>>>(cb);

    void *dst = nullptr, *src = nullptr;
    cudaGetSymbolAddress(&dst, c_tbl);
    cudaGetSymbolAddress(&src, g_stage);
    cudaMemcpyAsync(dst, src, sizeof(Tbl), cudaMemcpyDeviceToDevice, 0);

    tp_kernel<<<grid, TPB, SMEM_TOT>>>(in1, in2, out, B);
}

// round 17
// speedup vs baseline: 1.0165x; 1.0165x over previous
#include <cuda_runtime.h>
#include <cuda_fp16.h>
#include <cstdint>

// out[b,k] = sum_ij in1[b,i]*in2[b,j]*cb[k,ij]
// R16 design (TPB 128, CHUNK 8, division-free flush, fp16 P / fp32 O,
// constant-port meta) with the spill fixed: __launch_bounds__(128, 8) ->
// exactly 64 regs (128*8*64 = 65,536 = full RF), 8 CTAs/SM = 32 warps (50%).
// R16's regression was the 56-reg cap at occupancy 9 spilling the prologue
// arrays to local (+70 MB DRAM, issue 27%).

#define NK     81
#define NIJ    81
#define TPB    128
#define CHUNK  8
#define NPH    11
#define KPAD   (NPH * CHUNK)     // 88
#define OSTR   132               // O stride in floats; 132%32=4 -> flush banks
                                 // (4*kq+bl) injective over a warp

#define P_BYTES  (NIJ * TPB * 2)          // 20,736
#define O_BYTES  (CHUNK * OSTR * 4)       // 4,224
#define SMEM_TOT (P_BYTES + O_BYTES)      // 24,960 -> 8 CTAs/SM (199,680 B)

struct Tbl {
    float4 meta[KPAD][2];   // per k: {P_byteoff0,w0,off1,w1} x2 (off = ij*256)
    int    ovp[NPH + 1];    // overflow rowptr per phase
    int    pad[3];
};

__device__ Tbl    g_stage;
__device__ float4 g_ovf[NK * NIJ];   // {o_byteoff (kl*528), p_byteoff, w, 0}
__constant__ Tbl  c_tbl;

__global__ void prep_kernel(const float* __restrict__ cb) {
    __shared__ int ocnt[NK];
    __shared__ int ooff[NK + 1];
    const int k = threadIdx.x;
    if (k < NK) {
        int c = 0;
        for (int ij = 0; ij < NIJ; ij++)
            if (cb[k * NIJ + ij] != 0.f) c++;
        ocnt[k] = (c > 4) ? (c - 4) : 0;
    }
    __syncthreads();
    if (k == 0) {
        int s = 0;
        for (int q = 0; q < NK; q++) { ooff[q] = s; s += ocnt[q]; }
        ooff[NK] = s;
        for (int p = 0; p <= NPH; p++) {
            int kb = p * CHUNK; if (kb > NK) kb = NK;
            g_stage.ovp[p] = ooff[kb];
        }
    }
    __syncthreads();
    if (k < KPAD) {
        float id[4] = {0.f, 0.f, 0.f, 0.f};
        float w [4] = {0.f, 0.f, 0.f, 0.f};
        if (k < NK) {
            int n = 0;
            int o = ooff[k];
            const int kl = k & (CHUNK - 1);
            for (int ij = 0; ij < NIJ; ij++) {
                float v = cb[k * NIJ + ij];
                if (v != 0.f) {
                    if (n < 4) { id[n] = __int_as_float(ij * TPB * 2); w[n] = v; n++; }
                    else g_ovf[o++] = make_float4(__int_as_float(kl * OSTR * 4),
                                                  __int_as_float(ij * TPB * 2), v, 0.f);
                }
            }
        }
        g_stage.meta[k][0] = make_float4(id[0], w[0], id[1], w[1]);
        g_stage.meta[k][1] = make_float4(id[2], w[2], id[3], w[3]);
    }
}

__global__ void __launch_bounds__(TPB, 8) tp_kernel(
    const float* __restrict__ in1,
    const float* __restrict__ in2,
    float* __restrict__ out,
    int B)
{
    extern __shared__ char smemc[];
    __half* P   = (__half*)smemc;                  // [81][128] halves
    float*  O   = (float*)(smemc + P_BYTES);       // [8][132] floats
    float*  st1 = (float*)smemc;                   // staging (P region)
    float*  st2 = (float*)(smemc + TPB * 9 * 4);   // +4608 B, 16B-aligned

    const int t = threadIdx.x;
    const int base = blockIdx.x * TPB;

    // ---- coalesced input staging into the (not-yet-used) P region ----
    const int avail = B * 9 - base * 9;
    if (avail >= TPB * 9) {
        const float4* v1 = (const float4*)(in1 + base * 9);  // base*36 % 16 == 0
        const float4* v2 = (const float4*)(in2 + base * 9);
        float4* s1 = (float4*)st1;
        float4* s2 = (float4*)st2;
#pragma unroll
        for (int q = t; q < (TPB * 9) / 4; q += TPB) { s1[q] = v1[q]; s2[q] = v2[q]; }
    } else {
        for (int q = t; q < TPB * 9; q += TPB) {
            bool ok = q < avail;
            st1[q] = ok ? in1[base * 9 + q] : 0.f;
            st2[q] = ok ? in2[base * 9 + q] : 0.f;
        }
    }
    __syncthreads();

    float a[9], c9[9];                 // bank 9t+i mod 32, gcd(9,32)=1: clean
#pragma unroll
    for (int i = 0; i < 9; i++) { a[i] = st1[t * 9 + i]; c9[i] = st2[t * 9 + i]; }
    __syncthreads();                   // staging consumed; P region free

    // outer product -> fp16 P, own column (only this thread reads it)
    char* Pb = (char*)P + t * 2;
#pragma unroll
    for (int i = 0; i < 9; i++)
#pragma unroll
        for (int j = 0; j < 9; j++)
            *(__half*)(Pb + (i * 9 + j) * (TPB * 2)) = __float2half_rn(a[i] * c9[j]);

    const int limit  = B * NK;                   // 84,934,656 < 2^31
    const int gbase0 = blockIdx.x * TPB * NK;
    const bool full  = (base + TPB) * NK <= limit;
    char* Ob = (char*)O + t * 4;

    const int bl0 = t >> 3;            // flush: fixed per-thread decomposition
    const int kq0 = t & 7;

#pragma unroll
    for (int ph = 0; ph < NPH; ph++) {
        // ---- contraction: fixed 4 nnz per k, immediate constant addresses ----
#pragma unroll
        for (int kq = 0; kq < CHUNK; kq++) {
            const float4 m0 = c_tbl.meta[ph * CHUNK + kq][0];
            const float4 m1 = c_tbl.meta[ph * CHUNK + kq][1];
            float p0 = __half2float(*(const __half*)(Pb + __float_as_int(m0.x)));
            float p1 = __half2float(*(const __half*)(Pb + __float_as_int(m0.z)));
            float p2 = __half2float(*(const __half*)(Pb + __float_as_int(m1.x)));
            float p3 = __half2float(*(const __half*)(Pb + __float_as_int(m1.z)));
            float s0 = m0.y * p0;
            float s1 = m0.w * p1;
            s0 = fmaf(m1.y, p2, s0);
            s1 = fmaf(m1.w, p3, s1);
            *(float*)(Ob + kq * (OSTR * 4)) = s0 + s1;   // STS consecutive-t
        }
        // ---- rare overflow entries (rows with >4 nnz), own-column += ----
        {
            const int r1 = c_tbl.ovp[ph + 1];
#pragma unroll 1
            for (int r = c_tbl.ovp[ph]; r < r1; r++) {
                const float4 e = g_ovf[r];
                float pv = __half2float(*(const __half*)(Pb + __float_as_int(e.y)));
                float* op = (float*)(Ob + __float_as_int(e.x));
                *op = fmaf(e.z, pv, *op);
            }
        }
        __syncthreads();   // flush reads other threads' O columns

        // ---- flush: conflict-free LDS, constant deltas, coalesced STG ----
        if (ph < 10) {
            int si = kq0 * OSTR + bl0;                 // (4kq+bl)%32 injective
            int g  = gbase0 + bl0 * NK + ph * CHUNK + kq0;
            if (full) {
#pragma unroll
                for (int r = 0; r < TPB / 16; r++) {   // 8 iters: 16 rows/iter
                    out[g] = O[si];
                    g  += 16 * NK;                     // 1296
                    si += 16;
                }
            } else {
#pragma unroll
                for (int r = 0; r < TPB / 16; r++) {
                    if (g < limit) out[g] = O[si];
                    g  += 16 * NK;
                    si += 16;
                }
            }
        } else {            // ph == 10: only k = 80 (kq0 == 0) is real
            if (kq0 == 0) {
                int si = bl0;
                int g  = gbase0 + bl0 * NK + 80;
#pragma unroll
                for (int r = 0; r < TPB / 16; r++) {
                    if (g < limit) out[g] = O[si];
                    g  += 16 * NK;
                    si += 16;
                }
            }
        }
        __syncthreads();   // next phase reuses O
    }
}

extern "C" void kernel_launch(void* const* d_in, const int* in_sizes, int n_in,
                              void* d_out, int out_size) {
    const float* in1 = (const float*)d_in[0];
    const float* in2 = (const float*)d_in[1];
    const float* cb  = (const float*)d_in[2];
    float* out = (float*)d_out;

    const int B = in_sizes[0] / 9;
    const int grid = (B + TPB - 1) / TPB;

    cudaFuncSetAttribute(tp_kernel,
                         cudaFuncAttributeMaxDynamicSharedMemorySize,
                         SMEM_TOT);      // 24,960 B -> 8 CTAs/SM

    prep_kernel<<<1, 128>>>(cb);

    void *dst = nullptr, *src = nullptr;
    cudaGetSymbolAddress(&dst, c_tbl);
    cudaGetSymbolAddress(&src, g_stage);
    cudaMemcpyAsync(dst, src, sizeof(Tbl), cudaMemcpyDeviceToDevice, 0);

    tp_kernel<<<grid, TPB, SMEM_TOT>>>(in1, in2, out, B);
}